// round 14
// baseline (speedup 1.0000x reference)
#include <cuda_runtime.h>
#include <cstdint>

#define H        768
#define CK       16                    // K floats per pipeline stage (64 B/row)
#define NCH      (H / CK)              // 48 chunks
#define DEPTH    3                     // cp.async ring stages (2 chunks in flight)
#define WROWS    128                   // rows per warp pass (4 per lane)
#define G        4                     // rows per lane
#define CHUNK_FLOATS (WROWS * CK)      // 2048 floats = 8192 B (no padding)
#define CHUNK_BYTES  (CHUNK_FLOATS * 4)
#define WARPS    7                     // warps per CTA (224 threads), 1 CTA/SM
#define W4_FLOATS (H * 16)             // [H][4] float4 region (48 KB)
#define W1_FLOATS (H)                  // [H] float region (3 KB)
#define WX_FLOATS (W4_FLOATS + W1_FLOATS)
#define SMEM_BYTES ((WX_FLOATS + WARPS * DEPTH * CHUNK_FLOATS) * 4)  // 224256 B

// 17 fused channels: a0,a1 | b0..b3 | c1_0,c1_1 | c2_0..2 | c3_0..3 | c4_0,c4_1
__constant__ float c_bias[17];

__device__ float4 g_pack4[H * 4];      // channels 0..15, [k][p]
__device__ float  g_pack1[H];          // channel 16
__device__ float  g_biasStage[17];
__device__ unsigned int g_ticket;

// ---------------------------------------------------------------------------
__global__ void prep_kernel(
    const float* __restrict__ Wa,  const float* __restrict__ ba,
    const float* __restrict__ Wb,  const float* __restrict__ bb,
    const float* __restrict__ Wc1, const float* __restrict__ bc1,
    const float* __restrict__ Wc2, const float* __restrict__ bc2,
    const float* __restrict__ Wc3, const float* __restrict__ bc3,
    const float* __restrict__ Wc4, const float* __restrict__ bc4)
{
    int id = blockIdx.x * blockDim.x + threadIdx.x;
    if (id == 0) g_ticket = 0u;

    auto getw = [&](int ch, int k) -> float {
        if (ch < 2)  return Wa [ ch        * H + k];
        if (ch < 6)  return Wb [(ch - 2)  * H + k];
        if (ch < 8)  return Wc1[(ch - 6)  * H + k];
        if (ch < 11) return Wc2[(ch - 8)  * H + k];
        if (ch < 15) return Wc3[(ch - 11) * H + k];
        return Wc4[(ch - 15) * H + k];
    };

    if (id < H * 4) {
        int k = id >> 2, p = id & 3;
        g_pack4[id] = make_float4(getw(4 * p, k),     getw(4 * p + 1, k),
                                  getw(4 * p + 2, k), getw(4 * p + 3, k));
    }
    if (id < H) g_pack1[id] = getw(16, id);
    if (id < 17) {
        int ch = id; float b;
        if      (ch < 2)  b = ba [ch];
        else if (ch < 6)  b = bb [ch - 2];
        else if (ch < 8)  b = bc1[ch - 6];
        else if (ch < 11) b = bc2[ch - 8];
        else if (ch < 15) b = bc3[ch - 11];
        else              b = bc4[ch - 15];
        g_biasStage[ch] = b;
    }
}

// ---------------------------------------------------------------------------
__device__ __forceinline__ void ffma2(float2& d, const float2 a, const float2 b)
{
    asm("fma.rn.f32x2 %0, %1, %2, %0;"
        : "+l"(reinterpret_cast<unsigned long long&>(d))
        : "l"(reinterpret_cast<const unsigned long long&>(a)),
          "l"(reinterpret_cast<const unsigned long long&>(b)));
}

__device__ __forceinline__ void cp16(uint32_t saddr, const void* gptr)
{
    asm volatile("cp.async.cg.shared.global [%0], [%1], 16;"
                 :: "r"(saddr), "l"(gptr) : "memory");
}
__device__ __forceinline__ void cp_commit()
{
    asm volatile("cp.async.commit_group;" ::: "memory");
}
template <int N>
__device__ __forceinline__ void cp_wait()
{
    asm volatile("cp.async.wait_group %0;" :: "n"(N) : "memory");
}

// ---------------------------------------------------------------------------
// Staging layout per (warp, ring slot): xs[4 jg][128 rows][4 floats] (8 KB).
//   read : LDS.128 at float-offset jg*512 + r*4   (granule = r mod 8, CF)
//   store: cp16 at byte-offset jg*2048 + r*16     (4 x 128B contiguous / inst)
// 128-row pass per warp (4 rows/lane); 3-deep cp.async ring = 16 KB in flight
// per warp -> 112 KB/SM. Weights in shared memory. 7 warps/CTA, 1 CTA/SM;
// 1024 passes over 1036 warp slots (1:1).
// ---------------------------------------------------------------------------
extern __shared__ float smem[];

__global__ void __launch_bounds__(WARPS * 32)
main_kernel(const float* __restrict__ x, float* __restrict__ out, int B, int npasses)
{
    const int wid  = threadIdx.x >> 5;
    const int lane = threadIdx.x & 31;

    float4* sw4   = reinterpret_cast<float4*>(smem);    // [H][4]
    float*  sw1   = smem + W4_FLOATS;                   // [H]
    float*  xbase = smem + WX_FLOATS;

    // ---- stage weights into smem once per CTA ----
    for (int i = threadIdx.x; i < H * 4; i += WARPS * 32)
        sw4[i] = g_pack4[i];
    for (int i = threadIdx.x; i < H; i += WARPS * 32)
        sw1[i] = g_pack1[i];
    __syncthreads();

    const uint32_t sb = (uint32_t)__cvta_generic_to_shared(xbase)
                        + wid * (DEPTH * CHUNK_BYTES);
    float* xw = xbase + wid * (DEPTH * CHUNK_FLOATS);

    // cp.async mapping: 4 lanes x 16 B cover one 64 B row segment; 8 rows/inst
    const int crow  = lane >> 2;   // 0..7
    const int cpart = lane & 3;    // 0..3 == jg

    for (;;) {
        unsigned t;
        if (lane == 0) t = atomicAdd(&g_ticket, 1u);
        t = __shfl_sync(0xffffffffu, t, 0);
        if (t >= (unsigned)npasses) break;

        const int    row0 = (int)t * WROWS;
        const float* gx   = x + (size_t)row0 * H;

        auto load_chunk = [&](int c, int d) {
            const float*   gsrc = gx + c * CK + (size_t)crow * H + cpart * 4;
            const uint32_t dst0 = sb + d * CHUNK_BYTES + cpart * 2048 + crow * 16;
            #pragma unroll
            for (int i = 0; i < 16; ++i) {         // 16 x 8 rows = 128 rows
                if (row0 + i * 8 + crow < B)
                    cp16(dst0 + i * 8 * 16, gsrc + (size_t)(i * 8) * H);
            }
        };

        float2 acc[G][8];
        float  a16[G];
        #pragma unroll
        for (int g = 0; g < G; ++g) {
            #pragma unroll
            for (int p = 0; p < 8; ++p) acc[g][p] = make_float2(0.f, 0.f);
            a16[g] = 0.f;
        }

        cp_wait<0>();                 // drain leftover groups from prior pass
        load_chunk(0, 0); cp_commit();
        load_chunk(1, 1); cp_commit();
        load_chunk(2, 2); cp_commit();

        int slot = 0;                 // ring slot of chunk c (incremental, no %)
        #pragma unroll 1
        for (int c = 0; c < NCH; ++c) {
            cp_wait<DEPTH - 1>();     // chunk c resident (2 newer groups flying)
            __syncwarp();

            const float* xb = xw + slot * CHUNK_FLOATS;
            const int kc = c * CK;
            #pragma unroll
            for (int jg = 0; jg < 4; ++jg) {
                float4 xv[G];
                #pragma unroll
                for (int g = 0; g < G; ++g)
                    xv[g] = *reinterpret_cast<const float4*>(
                        xb + jg * 512 + (lane + 32 * g) * 4);

                const int kb = kc + jg * 4;
                #pragma unroll
                for (int j = 0; j < 4; ++j) {
                    const int k = kb + j;
                    const float4* wk = sw4 + k * 4;     // warp-uniform -> broadcast LDS
                    const float4 w0 = wk[0];
                    const float4 w1 = wk[1];
                    const float4 w2 = wk[2];
                    const float4 w3 = wk[3];
                    const float  wl = sw1[k];
                    #pragma unroll
                    for (int g = 0; g < G; ++g) {
                        const float xk = (j == 0) ? xv[g].x : (j == 1) ? xv[g].y
                                       : (j == 2) ? xv[g].z : xv[g].w;
                        const float2 xd = make_float2(xk, xk);
                        ffma2(acc[g][0], xd, make_float2(w0.x, w0.y));
                        ffma2(acc[g][1], xd, make_float2(w0.z, w0.w));
                        ffma2(acc[g][2], xd, make_float2(w1.x, w1.y));
                        ffma2(acc[g][3], xd, make_float2(w1.z, w1.w));
                        ffma2(acc[g][4], xd, make_float2(w2.x, w2.y));
                        ffma2(acc[g][5], xd, make_float2(w2.z, w2.w));
                        ffma2(acc[g][6], xd, make_float2(w3.x, w3.y));
                        ffma2(acc[g][7], xd, make_float2(w3.z, w3.w));
                        a16[g] = fmaf(xk, wl, a16[g]);
                    }
                }
            }
            __syncwarp();

            // refill the buffer just consumed: slot(c+DEPTH) == slot(c)
            if (c + DEPTH < NCH) load_chunk(c + DEPTH, slot);
            cp_commit();              // empty groups keep wait_group counts exact

            slot = (slot == DEPTH - 1) ? 0 : slot + 1;
        }

        // --- epilogue: bias, routing, masked scattered stores (4 rows/lane) ---
        #pragma unroll
        for (int g = 0; g < G; ++g) {
            const int r = row0 + lane + 32 * g;
            if (r >= B) continue;

            float v[17];
            #pragma unroll
            for (int p = 0; p < 8; ++p) {
                v[2 * p]     = acc[g][p].x + c_bias[2 * p];
                v[2 * p + 1] = acc[g][p].y + c_bias[2 * p + 1];
            }
            v[16] = a16[g] + c_bias[16];

            const bool active = v[1] > v[0];               // argmax(out_a) != 0

            ((float2*)out)[r] = make_float2(v[0], v[1]);   // out_a

            int pb = 0; float best = v[2];
            if (v[3] > best) { pb = 1; best = v[3]; }
            if (v[4] > best) { pb = 2; best = v[4]; }
            if (v[5] > best) { pb = 3; best = v[5]; }

            float* ob = out + 2 * (size_t)B + 5 * (size_t)r;   // out_b
            ob[0] = 0.0f;
            #pragma unroll
            for (int j = 0; j < 4; ++j) ob[j + 1] = active ? v[2 + j] : 0.0f;

            float* oc = out + 7 * (size_t)B + 11 * (size_t)r;  // out_c
            #pragma unroll
            for (int j = 0; j < 11; ++j) {
                const int hd = (j < 2) ? 0 : (j < 5) ? 1 : (j < 9) ? 2 : 3;
                oc[j] = (active && hd == pb) ? v[6 + j] : 0.0f;
            }
        }
    }
}

// ---------------------------------------------------------------------------
extern "C" void kernel_launch(void* const* d_in, const int* in_sizes, int n_in,
                              void* d_out, int out_size)
{
    const float* x = (const float*)d_in[0];
    const int B = in_sizes[0] / H;

    prep_kernel<<<12, 256>>>(
        (const float*)d_in[1],  (const float*)d_in[2],
        (const float*)d_in[3],  (const float*)d_in[4],
        (const float*)d_in[5],  (const float*)d_in[6],
        (const float*)d_in[7],  (const float*)d_in[8],
        (const float*)d_in[9],  (const float*)d_in[10],
        (const float*)d_in[11], (const float*)d_in[12]);

    void* pb = nullptr; cudaGetSymbolAddress(&pb, g_biasStage);
    cudaMemcpyToSymbolAsync(c_bias, pb, sizeof(float) * 17, 0,
                            cudaMemcpyDeviceToDevice, 0);

    const int npasses = (B + WROWS - 1) / WROWS;   // 1024 for B=131072
    const int grid    = 148;                        // 1 CTA/SM, 1036 warp slots

    cudaFuncSetAttribute(main_kernel,
                         cudaFuncAttributeMaxDynamicSharedMemorySize, SMEM_BYTES);
    main_kernel<<<grid, WARPS * 32, SMEM_BYTES>>>(x, (float*)d_out, B, npasses);
}

// round 15
// speedup vs baseline: 1.5962x; 1.5962x over previous
#include <cuda_runtime.h>
#include <cstdint>

#define H        768
#define CK       32                    // K floats per stage = 128 B/row (FULL lines)
#define NCH      (H / CK)              // 24 chunks
#define DEPTH    2                     // ring stages per pair
#define WROWS    128                   // rows per PAIR tile (4 per lane per warp)
#define G        4                     // rows per lane
#define RSTR     36                    // floats per row slot (32 + 4 pad -> 144 B)
#define CHUNK_FLOATS (WROWS * RSTR)    // 4608
#define CHUNK_BYTES  (CHUNK_FLOATS * 4)  // 18432
#define WARPS    8                     // 4 pairs, 256 threads, 1 CTA/SM
#define NPAIRS   (WARPS / 2)
#define W4_FLOATS (H * 16)             // [H][4] float4 (48 KB)
#define W1_FLOATS (H)                  // [H] float (3 KB)
#define WX_FLOATS (W4_FLOATS + W1_FLOATS)
#define TICK_FLOATS 8
#define SMEM_BYTES ((WX_FLOATS + NPAIRS * DEPTH * CHUNK_FLOATS + TICK_FLOATS) * 4) // ~199.7 KB

// 17 fused channels: a0,a1 | b0..b3 | c1_0,c1_1 | c2_0..2 | c3_0..3 | c4_0,c4_1
__constant__ float c_bias[17];

__device__ float4 g_pack4[H * 4];
__device__ float  g_pack1[H];
__device__ float  g_biasStage[17];
__device__ unsigned int g_ticket;

// ---------------------------------------------------------------------------
__global__ void prep_kernel(
    const float* __restrict__ Wa,  const float* __restrict__ ba,
    const float* __restrict__ Wb,  const float* __restrict__ bb,
    const float* __restrict__ Wc1, const float* __restrict__ bc1,
    const float* __restrict__ Wc2, const float* __restrict__ bc2,
    const float* __restrict__ Wc3, const float* __restrict__ bc3,
    const float* __restrict__ Wc4, const float* __restrict__ bc4)
{
    int id = blockIdx.x * blockDim.x + threadIdx.x;
    if (id == 0) g_ticket = 0u;

    auto getw = [&](int ch, int k) -> float {
        if (ch < 2)  return Wa [ ch        * H + k];
        if (ch < 6)  return Wb [(ch - 2)  * H + k];
        if (ch < 8)  return Wc1[(ch - 6)  * H + k];
        if (ch < 11) return Wc2[(ch - 8)  * H + k];
        if (ch < 15) return Wc3[(ch - 11) * H + k];
        return Wc4[(ch - 15) * H + k];
    };

    if (id < H * 4) {
        int k = id >> 2, p = id & 3;
        g_pack4[id] = make_float4(getw(4 * p, k),     getw(4 * p + 1, k),
                                  getw(4 * p + 2, k), getw(4 * p + 3, k));
    }
    if (id < H) g_pack1[id] = getw(16, id);
    if (id < 17) {
        int ch = id; float b;
        if      (ch < 2)  b = ba [ch];
        else if (ch < 6)  b = bb [ch - 2];
        else if (ch < 8)  b = bc1[ch - 6];
        else if (ch < 11) b = bc2[ch - 8];
        else if (ch < 15) b = bc3[ch - 11];
        else              b = bc4[ch - 15];
        g_biasStage[ch] = b;
    }
}

// ---------------------------------------------------------------------------
__device__ __forceinline__ void ffma2(float2& d, const float2 a, const float2 b)
{
    asm("fma.rn.f32x2 %0, %1, %2, %0;"
        : "+l"(reinterpret_cast<unsigned long long&>(d))
        : "l"(reinterpret_cast<const unsigned long long&>(a)),
          "l"(reinterpret_cast<const unsigned long long&>(b)));
}

__device__ __forceinline__ void cp16(uint32_t saddr, const void* gptr)
{
    asm volatile("cp.async.cg.shared.global [%0], [%1], 16;"
                 :: "r"(saddr), "l"(gptr) : "memory");
}
__device__ __forceinline__ void cp_commit()
{
    asm volatile("cp.async.commit_group;" ::: "memory");
}
template <int N>
__device__ __forceinline__ void cp_wait()
{
    asm volatile("cp.async.wait_group %0;" :: "n"(N) : "memory");
}
__device__ __forceinline__ void pair_bar(int pair)
{
    asm volatile("bar.sync %0, 64;" :: "r"(pair + 1) : "memory");
}

// ---------------------------------------------------------------------------
// Warp-pair cooperative kernel: a pair shares a 128-row x CK=32 staged chunk
// (full 128B gmem lines per cp inst). Warp pw computes k-cols pw*16..pw*16+15
// for all 128 rows (4/lane); partials combined through smem once per pass.
// ---------------------------------------------------------------------------
extern __shared__ float smem[];

__global__ void __launch_bounds__(WARPS * 32)
main_kernel(const float* __restrict__ x, float* __restrict__ out, int B, int npasses)
{
    const int wid  = threadIdx.x >> 5;
    const int lane = threadIdx.x & 31;
    const int pair = wid >> 1;
    const int pw   = wid & 1;          // which k-half this warp owns

    float4* sw4   = reinterpret_cast<float4*>(smem);    // [H][4]
    float*  sw1   = smem + W4_FLOATS;                   // [H]
    float*  xbase = smem + WX_FLOATS;
    int*    stick = reinterpret_cast<int*>(xbase + NPAIRS * DEPTH * CHUNK_FLOATS);

    // ---- stage weights into smem once per CTA ----
    for (int i = threadIdx.x; i < H * 4; i += WARPS * 32)
        sw4[i] = g_pack4[i];
    for (int i = threadIdx.x; i < H; i += WARPS * 32)
        sw1[i] = g_pack1[i];
    __syncthreads();                   // bar 0, never used again

    float* xw = xbase + pair * (DEPTH * CHUNK_FLOATS);
    const uint32_t sb = (uint32_t)__cvta_generic_to_shared(xw);

    // cp mapping: 8 lanes x 16B = one FULL 128B row line; 4 rows per inst.
    const int lrow  = lane >> 3;       // 0..3
    const int lpart = lane & 7;        // 0..7
    const int rbase = pw * 4 + lrow;   // this warp covers rows = i*8 + rbase

    const int co = pw * 16;            // this warp's k-column offset in chunk

    for (;;) {
        if (pw == 0 && lane == 0) stick[pair] = (int)atomicAdd(&g_ticket, 1u);
        pair_bar(pair);                // publish ticket; also fences prior epilogue
        const int t = stick[pair];
        if (t >= npasses) break;

        const int    row0 = t * WROWS;
        const float* gx   = x + (size_t)row0 * H;

        // each warp loads its 64 rows (r % 8 in [pw*4, pw*4+4)) of chunk c
        auto load_half = [&](int c, int slot) {
            const float*   gsrc = gx + c * CK + (size_t)rbase * H + lpart * 4;
            const uint32_t dst0 = sb + slot * CHUNK_BYTES + rbase * (RSTR * 4)
                                     + lpart * 16;
            #pragma unroll
            for (int i = 0; i < 16; ++i) {
                if (row0 + i * 8 + rbase < B)
                    cp16(dst0 + i * 8 * (RSTR * 4), gsrc + (size_t)(i * 8) * H);
            }
        };

        float2 acc[G][8];
        float  a16[G];
        #pragma unroll
        for (int g = 0; g < G; ++g) {
            #pragma unroll
            for (int p = 0; p < 8; ++p) acc[g][p] = make_float2(0.f, 0.f);
            a16[g] = 0.f;
        }

        load_half(0, 0); cp_commit();
        load_half(1, 1); cp_commit();

        int slot = 0;
        #pragma unroll 2
        for (int c = 0; c < NCH; ++c) {
            cp_wait<DEPTH - 1>();      // this warp's half of chunk c landed
            pair_bar(pair);            // partner's half landed too

            const float* xb = xw + slot * CHUNK_FLOATS;
            const int kc = c * CK + co;
            #pragma unroll
            for (int jg = 0; jg < 4; ++jg) {
                float4 xv[G];
                #pragma unroll
                for (int g = 0; g < G; ++g)
                    xv[g] = *reinterpret_cast<const float4*>(
                        xb + (lane + 32 * g) * RSTR + co + jg * 4);

                const int kb = kc + jg * 4;
                #pragma unroll
                for (int j = 0; j < 4; ++j) {
                    const int k = kb + j;
                    const float4* wk = sw4 + k * 4;   // warp-uniform -> broadcast LDS
                    const float4 w0 = wk[0];
                    const float4 w1 = wk[1];
                    const float4 w2 = wk[2];
                    const float4 w3 = wk[3];
                    const float  wl = sw1[k];
                    #pragma unroll
                    for (int g = 0; g < G; ++g) {
                        const float xk = (j == 0) ? xv[g].x : (j == 1) ? xv[g].y
                                       : (j == 2) ? xv[g].z : xv[g].w;
                        const float2 xd = make_float2(xk, xk);
                        ffma2(acc[g][0], xd, make_float2(w0.x, w0.y));
                        ffma2(acc[g][1], xd, make_float2(w0.z, w0.w));
                        ffma2(acc[g][2], xd, make_float2(w1.x, w1.y));
                        ffma2(acc[g][3], xd, make_float2(w1.z, w1.w));
                        ffma2(acc[g][4], xd, make_float2(w2.x, w2.y));
                        ffma2(acc[g][5], xd, make_float2(w2.z, w2.w));
                        ffma2(acc[g][6], xd, make_float2(w3.x, w3.y));
                        ffma2(acc[g][7], xd, make_float2(w3.z, w3.w));
                        a16[g] = fmaf(xk, wl, a16[g]);
                    }
                }
            }
            pair_bar(pair);            // both warps done reading this slot

            if (c + DEPTH < NCH) load_half(c + DEPTH, slot);
            cp_commit();               // empty groups keep wait counts exact

            slot ^= 1;
        }

        // --- combine k-halves through smem (reuse slot 0), then epilogue ---
        if (pw == 1) {
            #pragma unroll
            for (int g = 0; g < G; ++g) {
                const int r = lane + 32 * g;
                float* dst = xw + r * 20;
                #pragma unroll
                for (int p = 0; p < 8; ++p)
                    *reinterpret_cast<float2*>(dst + 2 * p) = acc[g][p];
                dst[16] = a16[g];
            }
        }
        pair_bar(pair);

        if (pw == 0) {
            #pragma unroll
            for (int g = 0; g < G; ++g) {
                const int r = row0 + lane + 32 * g;
                if (r >= B) continue;
                const float* src = xw + (lane + 32 * g) * 20;

                float v[17];
                #pragma unroll
                for (int p = 0; p < 8; ++p) {
                    const float2 o = *reinterpret_cast<const float2*>(src + 2 * p);
                    v[2 * p]     = acc[g][p].x + o.x + c_bias[2 * p];
                    v[2 * p + 1] = acc[g][p].y + o.y + c_bias[2 * p + 1];
                }
                v[16] = a16[g] + src[16] + c_bias[16];

                const bool active = v[1] > v[0];              // argmax(out_a) != 0

                ((float2*)out)[r] = make_float2(v[0], v[1]);  // out_a

                int pb = 0; float best = v[2];
                if (v[3] > best) { pb = 1; best = v[3]; }
                if (v[4] > best) { pb = 2; best = v[4]; }
                if (v[5] > best) { pb = 3; best = v[5]; }

                float* ob = out + 2 * (size_t)B + 5 * (size_t)r;   // out_b
                ob[0] = 0.0f;
                #pragma unroll
                for (int j = 0; j < 4; ++j) ob[j + 1] = active ? v[2 + j] : 0.0f;

                float* oc = out + 7 * (size_t)B + 11 * (size_t)r;  // out_c
                #pragma unroll
                for (int j = 0; j < 11; ++j) {
                    const int hd = (j < 2) ? 0 : (j < 5) ? 1 : (j < 9) ? 2 : 3;
                    oc[j] = (active && hd == pb) ? v[6 + j] : 0.0f;
                }
            }
        }
        // next iteration's pair_bar (after ticket) orders epilogue reads
        // before the new pass overwrites slot 0.
    }
}

// ---------------------------------------------------------------------------
extern "C" void kernel_launch(void* const* d_in, const int* in_sizes, int n_in,
                              void* d_out, int out_size)
{
    const float* x = (const float*)d_in[0];
    const int B = in_sizes[0] / H;

    prep_kernel<<<12, 256>>>(
        (const float*)d_in[1],  (const float*)d_in[2],
        (const float*)d_in[3],  (const float*)d_in[4],
        (const float*)d_in[5],  (const float*)d_in[6],
        (const float*)d_in[7],  (const float*)d_in[8],
        (const float*)d_in[9],  (const float*)d_in[10],
        (const float*)d_in[11], (const float*)d_in[12]);

    void* pb = nullptr; cudaGetSymbolAddress(&pb, g_biasStage);
    cudaMemcpyToSymbolAsync(c_bias, pb, sizeof(float) * 17, 0,
                            cudaMemcpyDeviceToDevice, 0);

    const int npasses = (B + WROWS - 1) / WROWS;   // 1024 for B=131072
    const int grid    = 148;                        // 1 CTA/SM, 592 pair slots

    cudaFuncSetAttribute(main_kernel,
                         cudaFuncAttributeMaxDynamicSharedMemorySize, SMEM_BYTES);
    main_kernel<<<grid, WARPS * 32, SMEM_BYTES>>>(x, (float*)d_out, B, npasses);
}